// round 8
// baseline (speedup 1.0000x reference)
#include <cuda_runtime.h>
#include <math.h>

// LSTM T=512, B=128, D_in=H=512.
//  prep:         repack weights gate-interleaved (col = j*4 + gate), reset barriers.
//  sgemm_x:      Gx[65536 x 2048] = X @ Wx + bias   (FFMA2 fp32 SGEMM)
//  lstm_persist: ONE kernel, 128 co-resident CTAs x 256 thr, 512 steps.
//                Wh slice smem-resident, c-state in registers, FFMA2 inner loop,
//                Gx prefetched at step start, per-row-group (ry) 32-CTA barriers.

#define T_STEPS 512
#define BATCH   128
#define HID     512
#define DIN     512
#define NG      2048
#define M_ALL   (T_STEPS * BATCH)
#define BH      (BATCH * HID)

__device__ float g_Gx[(size_t)M_ALL * NG];     // 512 MB scratch
__device__ float g_Wx[DIN * NG];
__device__ float g_Wh[HID * NG];
__device__ float g_bias[NG];
__device__ unsigned int g_bar_count[4];
__device__ unsigned int g_bar_gen[4];

typedef unsigned long long ull;
union F4U { float4 f; ull u[2]; float s[4]; };

__device__ __forceinline__ void ffma2(ull& d, ull a, ull b) {
    asm("fma.rn.f32x2 %0, %1, %2, %0;" : "+l"(d) : "l"(a), "l"(b));
}
__device__ __forceinline__ ull dup2(float x) {
    ull r;
    asm("mov.b64 %0, {%1, %1};" : "=l"(r) : "f"(x));
    return r;
}
__device__ __forceinline__ void unpk(ull v, float& lo, float& hi) {
    asm("mov.b64 {%0, %1}, %2;" : "=f"(lo), "=f"(hi) : "l"(v));
}
__device__ __forceinline__ float sigm(float x) {
    return __fdividef(1.0f, 1.0f + __expf(-x));
}
__device__ __forceinline__ float tanh_(float x) {
    return __fdividef(2.0f, 1.0f + __expf(-2.0f * x)) - 1.0f;
}

// ---------------------------------------------------------------------------
__global__ __launch_bounds__(256) void prep_kernel(
    const float* __restrict__ Wf, const float* __restrict__ bf,
    const float* __restrict__ Wi, const float* __restrict__ bi,
    const float* __restrict__ Wg, const float* __restrict__ bg,
    const float* __restrict__ Wo, const float* __restrict__ bo)
{
    int idx = blockIdx.x * 256 + threadIdx.x;
    if (idx < 4) { g_bar_count[idx] = 0; g_bar_gen[idx] = 0; }
    if (idx < DIN * NG) {
        int k   = idx / NG;
        int col = idx % NG;
        int j   = col >> 2;
        int g   = col & 3;
        const float* W = (g == 0) ? Wf : (g == 1) ? Wi : (g == 2) ? Wg : Wo;
        g_Wx[idx] = W[(size_t)k * HID + j];
        g_Wh[idx] = W[(size_t)(DIN + k) * HID + j];
        if (k == 0) {
            const float* b = (g == 0) ? bf : (g == 1) ? bi : (g == 2) ? bg : bo;
            g_bias[col] = b[j];
        }
    }
}

// ---------------------------------------------------------------------------
// Phase 1: Gx = X @ Wx + bias.  128x128 tile, BK=16, 256 thr, 8x8 microtile, FFMA2.
// ---------------------------------------------------------------------------
#define BM 128
#define BN 128
#define BK 16

__global__ __launch_bounds__(256) void sgemm_x(const float* __restrict__ A)
{
    __shared__ float As[BK][BM + 4];
    __shared__ float Bs[BK][BN];

    const int tid  = threadIdx.x;
    const int tx   = tid & 15;
    const int ty   = tid >> 4;
    const int row0 = blockIdx.y * BM;
    const int col0 = blockIdx.x * BN;

    ull acc[8][4];
    #pragma unroll
    for (int i = 0; i < 8; i++)
        #pragma unroll
        for (int jj = 0; jj < 4; jj++) acc[i][jj] = 0ull;

    for (int k0 = 0; k0 < DIN; k0 += BK) {
        #pragma unroll
        for (int i = 0; i < 2; i++) {
            int idx = tid + i * 256;
            int ar  = idx >> 2;
            int ak  = (idx & 3) << 2;
            float4 v = *(const float4*)(A + (size_t)(row0 + ar) * DIN + k0 + ak);
            As[ak + 0][ar] = v.x;
            As[ak + 1][ar] = v.y;
            As[ak + 2][ar] = v.z;
            As[ak + 3][ar] = v.w;
        }
        #pragma unroll
        for (int i = 0; i < 2; i++) {
            int idx = tid + i * 256;
            int br  = idx >> 5;
            int bc  = (idx & 31) << 2;
            *(float4*)&Bs[br][bc] =
                *(const float4*)(g_Wx + (size_t)(k0 + br) * NG + col0 + bc);
        }
        __syncthreads();

        #pragma unroll
        for (int k = 0; k < BK; k++) {
            F4U aA, aB, bA, bB;
            aA.f = *(float4*)&As[k][ty * 8];
            aB.f = *(float4*)&As[k][ty * 8 + 4];
            bA.f = *(float4*)&Bs[k][tx * 8];
            bB.f = *(float4*)&Bs[k][tx * 8 + 4];
            ull ad[8];
            #pragma unroll
            for (int i = 0; i < 4; i++) { ad[i] = dup2(aA.s[i]); ad[4 + i] = dup2(aB.s[i]); }
            #pragma unroll
            for (int i = 0; i < 8; i++) {
                ffma2(acc[i][0], ad[i], bA.u[0]);
                ffma2(acc[i][1], ad[i], bA.u[1]);
                ffma2(acc[i][2], ad[i], bB.u[0]);
                ffma2(acc[i][3], ad[i], bB.u[1]);
            }
        }
        __syncthreads();
    }

    #pragma unroll
    for (int i = 0; i < 8; i++) {
        int r = row0 + ty * 8 + i;
        int c = col0 + tx * 8;
        float o[8];
        unpk(acc[i][0], o[0], o[1]);
        unpk(acc[i][1], o[2], o[3]);
        unpk(acc[i][2], o[4], o[5]);
        unpk(acc[i][3], o[6], o[7]);
        float4 v0, v1;
        v0.x = o[0] + g_bias[c + 0]; v0.y = o[1] + g_bias[c + 1];
        v0.z = o[2] + g_bias[c + 2]; v0.w = o[3] + g_bias[c + 3];
        v1.x = o[4] + g_bias[c + 4]; v1.y = o[5] + g_bias[c + 5];
        v1.z = o[6] + g_bias[c + 6]; v1.w = o[7] + g_bias[c + 7];
        *(float4*)(g_Gx + (size_t)r * NG + c)     = v0;
        *(float4*)(g_Gx + (size_t)r * NG + c + 4) = v1;
    }
}

// ---------------------------------------------------------------------------
// Phase 2: persistent kernel. Grid (32 cx, 4 ry) = 128 CTAs, 256 threads.
// CTA(cx,ry): cols [cx*64, cx*64+64) = 16 hidden units x 4 gates,
//             rows [ry*32, ry*32+32).
// Wh slice (512x64 = 128KB) smem-resident; c in regs; h exchanged via d_out.
// Microtile 2 rows x 4 gate-cols / thread (tx = unit 0..15, ty = rowpair 0..15).
// Barrier: 4 independent per-ry 32-CTA sense barriers (CTA(cx,ry) only ever
// reads h rows produced by CTAs sharing its ry).
// ---------------------------------------------------------------------------
#define HSTRIDE 516
#define SMEM_PERSIST ((512 * 64 + 32 * HSTRIDE) * 4)

__global__ __launch_bounds__(256, 1) void lstm_persist(float* __restrict__ out,
                                                       int write_final)
{
    extern __shared__ float smem[];
    float* Ws = smem;              // [512][64]
    float* Hs = smem + 512 * 64;   // [32][HSTRIDE]

    const int tid      = threadIdx.x;
    const int tx       = tid & 15;
    const int ty       = tid >> 4;          // 0..15
    const int tx4      = tx << 2;
    const int col0     = blockIdx.x * 64;
    const int ry       = blockIdx.y;
    const int row_base = ry * 32;
    const int j        = (col0 >> 2) + tx;
    const int r0       = row_base + ty * 2;

    // Preload Wh slice into smem (once): 8192 float4, 32 per thread.
    #pragma unroll
    for (int i = 0; i < 32; i++) {
        int idx = tid + i * 256;
        int k   = idx >> 4;
        int c   = (idx & 15) << 2;
        *(float4*)&Ws[k * 64 + c] = *(const float4*)(g_Wh + (size_t)k * NG + col0 + c);
    }
    __syncthreads();

    float creg[2]  = {0.f, 0.f};
    float hlast[2] = {0.f, 0.f};

    const float* hs0 = &Hs[(ty * 2) * HSTRIDE];
    const float* hs1 = hs0 + HSTRIDE;

    for (int t = 0; t < T_STEPS; t++) {
        // Prefetch this step's Gx quad (consumed only in the epilogue;
        // DRAM latency hides under the ~8K-cycle GEMM below).
        const float4* gxp = (const float4*)(g_Gx + ((size_t)t * BATCH + r0) * NG + col0 + tx4);
        float4 gx0 = __ldg(gxp);
        float4 gx1 = __ldg(gxp + NG / 4);

        ull acc[2][2];
        acc[0][0] = acc[0][1] = acc[1][0] = acc[1][1] = 0ull;

        if (t > 0) {
            // Fill Hs with h_{t-1} rows [row_base, row_base+32): 4096 float4.
            const float* hp = out + (size_t)(t - 1) * BH;
            int hr = tid >> 3;              // 0..31
            int cb = tid & 7;               // 0..7
            #pragma unroll
            for (int i = 0; i < 16; i++) {
                int c4 = (cb + i * 8) << 2; // float col 0..508
                *(float4*)&Hs[hr * HSTRIDE + c4] =
                    *(const float4*)(hp + (size_t)(row_base + hr) * HID + c4);
            }
            __syncthreads();

            #pragma unroll 2
            for (int k = 0; k < HID; k += 4) {
                F4U a0, a1;
                a0.f = *(const float4*)(hs0 + k);
                a1.f = *(const float4*)(hs1 + k);
                #pragma unroll
                for (int kk = 0; kk < 4; kk++) {
                    F4U b;
                    b.f = *(const float4*)&Ws[(k + kk) * 64 + tx4];
                    ull d0 = dup2(a0.s[kk]);
                    ull d1 = dup2(a1.s[kk]);
                    ffma2(acc[0][0], d0, b.u[0]); ffma2(acc[0][1], d0, b.u[1]);
                    ffma2(acc[1][0], d1, b.u[0]); ffma2(acc[1][1], d1, b.u[1]);
                }
            }
        }

        // Fused LSTM epilogue: hidden unit j, rows r0, r0+1.
        float* orow = out + (size_t)t * BH;
        #pragma unroll
        for (int i = 0; i < 2; i++) {
            float4 gx = (i == 0) ? gx0 : gx1;
            float pf, pi, pg, po;
            unpk(acc[i][0], pf, pi);
            unpk(acc[i][1], pg, po);
            float f  = sigm(pf + gx.x);
            float ii = sigm(pi + gx.y);
            float g  = tanh_(pg + gx.z);
            float o  = sigm(po + gx.w);
            float cn = f * creg[i] + ii * g;
            creg[i]  = cn;
            float h  = o * tanh_(cn);
            hlast[i] = h;
            orow[(size_t)(r0 + i) * HID + j] = h;
        }

        // Per-ry 32-CTA barrier (release h_t to the row-group's readers).
        if (t < T_STEPS - 1) {
            __syncthreads();
            if (tid == 0) {
                __threadfence();
                unsigned int old = atomicAdd(&g_bar_count[ry], 1u);
                if (old == 31u) {
                    g_bar_count[ry] = 0;
                    __threadfence();
                    atomicAdd(&g_bar_gen[ry], 1u);
                } else {
                    unsigned int target = (unsigned int)(t + 1);
                    while (*(volatile unsigned int*)&g_bar_gen[ry] < target)
                        __nanosleep(20);
                }
                __threadfence();
            }
            __syncthreads();
        }
    }

    if (write_final) {
        size_t base = (size_t)T_STEPS * BH;
        #pragma unroll
        for (int i = 0; i < 2; i++) {
            out[base + (size_t)(r0 + i) * HID + j]      = hlast[i];
            out[base + BH + (size_t)(r0 + i) * HID + j] = creg[i];
        }
    }
}

// ---------------------------------------------------------------------------
extern "C" void kernel_launch(void* const* d_in, const int* in_sizes, int n_in,
                              void* d_out, int out_size)
{
    const float* x  = (const float*)d_in[0];
    const float* Wf = (const float*)d_in[1];
    const float* bf = (const float*)d_in[2];
    const float* Wi = (const float*)d_in[3];
    const float* bi = (const float*)d_in[4];
    const float* Wg = (const float*)d_in[5];
    const float* bg = (const float*)d_in[6];
    const float* Wo = (const float*)d_in[7];
    const float* bo = (const float*)d_in[8];
    float* out = (float*)d_out;

    static int attr_set = 0;
    if (!attr_set) {
        cudaFuncSetAttribute(lstm_persist,
                             cudaFuncAttributeMaxDynamicSharedMemorySize,
                             SMEM_PERSIST);
        attr_set = 1;
    }

    prep_kernel<<<(DIN * NG + 255) / 256, 256>>>(Wf, bf, Wi, bi, Wg, bg, Wo, bo);

    dim3 g1(NG / BN, M_ALL / BM);
    sgemm_x<<<g1, 256>>>(x);

    long long need = (long long)T_STEPS * BH + 2LL * BH;
    int wf = ((long long)out_size >= need) ? 1 : 0;
    lstm_persist<<<dim3(32, 4), 256, SMEM_PERSIST>>>(out, wf);
}

// round 9
// speedup vs baseline: 1.0194x; 1.0194x over previous
#include <cuda_runtime.h>
#include <math.h>

// LSTM T=512, B=128, D_in=H=512.  Two kernels only:
//  sgemm_x:      Gx[65536 x 2048] = X @ Wx + bias (gate-interleaved cols, FFMA2,
//                register double-buffered, streaming Gx stores). Also resets barriers.
//  lstm_persist: 128 co-resident CTAs x 256 thr, 512 steps, Wh smem-resident,
//                c in regs, scoped-atomic barriers (no fences, no L1 flush),
//                h exchanged through d_out via L2 (__stcg/__ldcg).

#define T_STEPS 512
#define BATCH   128
#define HID     512
#define DIN     512
#define NG      2048
#define M_ALL   (T_STEPS * BATCH)
#define BH      (BATCH * HID)

__device__ float g_Gx[(size_t)M_ALL * NG];          // 512 MB scratch
__device__ unsigned int g_bar[256];                 // [ry*64]=count, [ry*64+32]=gen

typedef unsigned long long ull;
union F4U { float4 f; ull u[2]; float s[4]; };

__device__ __forceinline__ void ffma2(ull& d, ull a, ull b) {
    asm("fma.rn.f32x2 %0, %1, %2, %0;" : "+l"(d) : "l"(a), "l"(b));
}
__device__ __forceinline__ ull dup2(float x) {
    ull r; asm("mov.b64 %0, {%1, %1};" : "=l"(r) : "f"(x)); return r;
}
__device__ __forceinline__ void unpk(ull v, float& lo, float& hi) {
    asm("mov.b64 {%0, %1}, %2;" : "=f"(lo), "=f"(hi) : "l"(v));
}
__device__ __forceinline__ float sigm(float x) {
    return __fdividef(1.0f, 1.0f + __expf(-x));
}
__device__ __forceinline__ float tanh_(float x) {
    return __fdividef(2.0f, 1.0f + __expf(-2.0f * x)) - 1.0f;
}
__device__ __forceinline__ unsigned atom_add_acqrel(unsigned* p, unsigned v) {
    unsigned old;
    asm volatile("atom.acq_rel.gpu.global.add.u32 %0, [%1], %2;"
                 : "=r"(old) : "l"(p), "r"(v) : "memory");
    return old;
}
__device__ __forceinline__ void red_add_release(unsigned* p, unsigned v) {
    asm volatile("red.release.gpu.global.add.u32 [%0], %1;"
                 :: "l"(p), "r"(v) : "memory");
}
__device__ __forceinline__ unsigned ld_acquire(const unsigned* p) {
    unsigned v;
    asm volatile("ld.acquire.gpu.global.u32 %0, [%1];"
                 : "=r"(v) : "l"(p) : "memory");
    return v;
}

// ---------------------------------------------------------------------------
// Phase 1: Gx = X @ Wx + bias.  128x128 tile, BK=16, 256 thr, 8x8 microtile,
// FFMA2, register double-buffering. B tile gathered gate-interleaved directly
// from the 4 weight arrays (col = j*4 + gate).
// ---------------------------------------------------------------------------
#define BM 128
#define BN 128
#define BK 16

__global__ __launch_bounds__(256, 2) void sgemm_x(
    const float* __restrict__ X,
    const float* __restrict__ Wf, const float* __restrict__ Wi,
    const float* __restrict__ Wg, const float* __restrict__ Wo,
    const float* __restrict__ bfp, const float* __restrict__ bip,
    const float* __restrict__ bgp, const float* __restrict__ bop)
{
    __shared__ float As[BK][BM + 4];
    __shared__ float Bs[BK][BN];

    const int tid  = threadIdx.x;
    const int tx   = tid & 15;
    const int ty   = tid >> 4;
    const int row0 = blockIdx.y * BM;
    const int col0 = blockIdx.x * BN;

    if (blockIdx.x == 0 && blockIdx.y == 0 && tid < 8)
        g_bar[(tid & 3) * 64 + (tid >> 2) * 32] = 0;   // reset persist barriers

    // A-load indices (2 float4/thread), B-gather indices (2x4 scalars/thread).
    const int ar0 = tid >> 2, ak0 = (tid & 3) << 2;
    const int ar1 = (tid + 256) >> 2, ak1 = ((tid + 256) & 3) << 2;
    const int br0 = tid >> 5, br1 = (tid + 256) >> 5;
    const int jj  = (col0 >> 2) + (tid & 31);
    const int bc  = (tid & 31) << 2;

    float4 pa0, pa1;
    float  pb0[4], pb1[4];

    // prologue: load tile k0=0
    pa0 = *(const float4*)(X + (size_t)(row0 + ar0) * DIN + ak0);
    pa1 = *(const float4*)(X + (size_t)(row0 + ar1) * DIN + ak1);
    {
        size_t o0 = (size_t)br0 * HID + jj, o1 = (size_t)br1 * HID + jj;
        pb0[0] = Wf[o0]; pb0[1] = Wi[o0]; pb0[2] = Wg[o0]; pb0[3] = Wo[o0];
        pb1[0] = Wf[o1]; pb1[1] = Wi[o1]; pb1[2] = Wg[o1]; pb1[3] = Wo[o1];
    }
    As[ak0 + 0][ar0] = pa0.x; As[ak0 + 1][ar0] = pa0.y;
    As[ak0 + 2][ar0] = pa0.z; As[ak0 + 3][ar0] = pa0.w;
    As[ak1 + 0][ar1] = pa1.x; As[ak1 + 1][ar1] = pa1.y;
    As[ak1 + 2][ar1] = pa1.z; As[ak1 + 3][ar1] = pa1.w;
    Bs[br0][bc + 0] = pb0[0]; Bs[br0][bc + 1] = pb0[1];
    Bs[br0][bc + 2] = pb0[2]; Bs[br0][bc + 3] = pb0[3];
    Bs[br1][bc + 0] = pb1[0]; Bs[br1][bc + 1] = pb1[1];
    Bs[br1][bc + 2] = pb1[2]; Bs[br1][bc + 3] = pb1[3];
    __syncthreads();

    ull acc[8][4];
    #pragma unroll
    for (int i = 0; i < 8; i++)
        #pragma unroll
        for (int j = 0; j < 4; j++) acc[i][j] = 0ull;

    for (int k0 = 0; k0 < DIN; k0 += BK) {
        const bool more = (k0 + BK) < DIN;
        if (more) {
            int kn = k0 + BK;
            pa0 = *(const float4*)(X + (size_t)(row0 + ar0) * DIN + kn + ak0);
            pa1 = *(const float4*)(X + (size_t)(row0 + ar1) * DIN + kn + ak1);
            size_t o0 = (size_t)(kn + br0) * HID + jj;
            size_t o1 = (size_t)(kn + br1) * HID + jj;
            pb0[0] = Wf[o0]; pb0[1] = Wi[o0]; pb0[2] = Wg[o0]; pb0[3] = Wo[o0];
            pb1[0] = Wf[o1]; pb1[1] = Wi[o1]; pb1[2] = Wg[o1]; pb1[3] = Wo[o1];
        }

        #pragma unroll
        for (int k = 0; k < BK; k++) {
            F4U aA, aB, bA, bB;
            aA.f = *(float4*)&As[k][ty * 8];
            aB.f = *(float4*)&As[k][ty * 8 + 4];
            bA.f = *(float4*)&Bs[k][tx * 8];
            bB.f = *(float4*)&Bs[k][tx * 8 + 4];
            ull ad[8];
            #pragma unroll
            for (int i = 0; i < 4; i++) { ad[i] = dup2(aA.s[i]); ad[4 + i] = dup2(aB.s[i]); }
            #pragma unroll
            for (int i = 0; i < 8; i++) {
                ffma2(acc[i][0], ad[i], bA.u[0]);
                ffma2(acc[i][1], ad[i], bA.u[1]);
                ffma2(acc[i][2], ad[i], bB.u[0]);
                ffma2(acc[i][3], ad[i], bB.u[1]);
            }
        }
        __syncthreads();
        if (more) {
            As[ak0 + 0][ar0] = pa0.x; As[ak0 + 1][ar0] = pa0.y;
            As[ak0 + 2][ar0] = pa0.z; As[ak0 + 3][ar0] = pa0.w;
            As[ak1 + 0][ar1] = pa1.x; As[ak1 + 1][ar1] = pa1.y;
            As[ak1 + 2][ar1] = pa1.z; As[ak1 + 3][ar1] = pa1.w;
            Bs[br0][bc + 0] = pb0[0]; Bs[br0][bc + 1] = pb0[1];
            Bs[br0][bc + 2] = pb0[2]; Bs[br0][bc + 3] = pb0[3];
            Bs[br1][bc + 0] = pb1[0]; Bs[br1][bc + 1] = pb1[1];
            Bs[br1][bc + 2] = pb1[2]; Bs[br1][bc + 3] = pb1[3];
            __syncthreads();
        }
    }

    // Epilogue: + bias (gathered), streaming store to g_Gx.
    const int ju0 = (col0 + tx * 8) >> 2;     // two hidden units per thread-col-block
    float b8[8];
    b8[0] = bfp[ju0];     b8[1] = bip[ju0];     b8[2] = bgp[ju0];     b8[3] = bop[ju0];
    b8[4] = bfp[ju0 + 1]; b8[5] = bip[ju0 + 1]; b8[6] = bgp[ju0 + 1]; b8[7] = bop[ju0 + 1];

    #pragma unroll
    for (int i = 0; i < 8; i++) {
        int r = row0 + ty * 8 + i;
        int c = col0 + tx * 8;
        float o[8];
        unpk(acc[i][0], o[0], o[1]);
        unpk(acc[i][1], o[2], o[3]);
        unpk(acc[i][2], o[4], o[5]);
        unpk(acc[i][3], o[6], o[7]);
        float4 v0 = make_float4(o[0] + b8[0], o[1] + b8[1], o[2] + b8[2], o[3] + b8[3]);
        float4 v1 = make_float4(o[4] + b8[4], o[5] + b8[5], o[6] + b8[6], o[7] + b8[7]);
        __stcs((float4*)(g_Gx + (size_t)r * NG + c),     v0);
        __stcs((float4*)(g_Gx + (size_t)r * NG + c + 4), v1);
    }
}

// ---------------------------------------------------------------------------
// Phase 2: persistent kernel. Grid (32 cx, 4 ry) = 128 CTAs, 256 threads.
// CTA(cx,ry): cols [cx*64, cx*64+64), rows [ry*32, ry*32+32).
// Warp map: wid&1 = col half (32 cols), wid>>1 = row quad (8 rows);
// lane: tx = lane&7 (col quad), tyl = lane>>3 (row pair). 2 rows x 4 cols/thr.
// ---------------------------------------------------------------------------
#define HSTRIDE 516
#define SMEM_PERSIST ((512 * 64 + 32 * HSTRIDE) * 4)

__global__ __launch_bounds__(256, 1) void lstm_persist(
    float* __restrict__ out, int write_final,
    const float* __restrict__ Wf, const float* __restrict__ Wi,
    const float* __restrict__ Wg, const float* __restrict__ Wo)
{
    extern __shared__ float smem[];
    float* Ws = smem;              // [512][64] gate-interleaved Wh slice
    float* Hs = smem + 512 * 64;   // [32][HSTRIDE]

    const int tid   = threadIdx.x;
    const int wid   = tid >> 5;
    const int lane  = tid & 31;
    const int tx    = lane & 7;
    const int tyl   = lane >> 3;
    const int chalf = wid & 1;
    const int rquad = wid >> 1;
    const int col0  = blockIdx.x * 64;
    const int ry    = blockIdx.y;
    const int row_base = ry * 32;

    const int cl = chalf * 32 + tx * 4;        // local col (4 gate cols = 1 unit)
    const int rl = rquad * 8 + tyl * 2;        // local row pair
    const int j  = (col0 >> 2) + chalf * 8 + tx;
    const int r0 = row_base + rl;

    unsigned* barc = &g_bar[ry * 64];
    unsigned* barg = &g_bar[ry * 64 + 32];

    // Preload gate-interleaved Wh slice into smem (once, gathered).
    {
        const int jbase = col0 >> 2;
        #pragma unroll
        for (int g = 0; g < 4; g++) {
            const float* Wp = (g == 0) ? Wf : (g == 1) ? Wi : (g == 2) ? Wg : Wo;
            for (int p = 0; p < 32; p++) {
                int idx = tid + p * 256;
                int k = idx >> 4, u = idx & 15;
                Ws[k * 64 + u * 4 + g] = Wp[(size_t)(DIN + k) * HID + jbase + u];
            }
        }
    }
    __syncthreads();

    float creg[2]  = {0.f, 0.f};
    float hlast[2] = {0.f, 0.f};

    const float* hs0 = &Hs[rl * HSTRIDE];
    const float* hs1 = hs0 + HSTRIDE;
    const int hr = tid >> 3;           // fill: row 0..31
    const int cb = tid & 7;            // fill: col phase

    for (int t = 0; t < T_STEPS; t++) {
        // Prefetch this step's Gx quads (epilogue-only; streaming).
        const float4* gxp = (const float4*)(g_Gx + ((size_t)t * BATCH + r0) * NG + col0 + cl);
        float4 gx0 = __ldcs(gxp);
        float4 gx1 = __ldcs(gxp + NG / 4);

        ull acc[2][2];
        acc[0][0] = acc[0][1] = acc[1][0] = acc[1][1] = 0ull;

        if (t > 0) {
            // Fill Hs with h_{t-1} rows [row_base, row_base+32) from L2.
            const float* hp = out + (size_t)(t - 1) * BH;
            #pragma unroll
            for (int i = 0; i < 16; i++) {
                int c4 = (cb + i * 8) << 2;
                float4 v = __ldcg((const float4*)(hp + (size_t)(row_base + hr) * HID + c4));
                *(float4*)&Hs[hr * HSTRIDE + c4] = v;
            }
            __syncthreads();

            #pragma unroll 2
            for (int k = 0; k < HID; k += 4) {
                F4U a0, a1;
                a0.f = *(const float4*)(hs0 + k);
                a1.f = *(const float4*)(hs1 + k);
                #pragma unroll
                for (int kk = 0; kk < 4; kk++) {
                    F4U b;
                    b.f = *(const float4*)&Ws[(k + kk) * 64 + cl];
                    ull d0 = dup2(a0.s[kk]);
                    ull d1 = dup2(a1.s[kk]);
                    ffma2(acc[0][0], d0, b.u[0]); ffma2(acc[0][1], d0, b.u[1]);
                    ffma2(acc[1][0], d1, b.u[0]); ffma2(acc[1][1], d1, b.u[1]);
                }
            }
        }

        // Fused LSTM epilogue: unit j, rows r0, r0+1. h stored via L2 (__stcg).
        float* orow = out + (size_t)t * BH;
        #pragma unroll
        for (int i = 0; i < 2; i++) {
            float4 gx = (i == 0) ? gx0 : gx1;
            float pf, pi, pg, po;
            unpk(acc[i][0], pf, pi);
            unpk(acc[i][1], pg, po);
            float f  = sigm(pf + gx.x);
            float ii = sigm(pi + gx.y);
            float g  = tanh_(pg + gx.z);
            float o  = sigm(po + gx.w);
            float cn = f * creg[i] + ii * g;
            creg[i]  = cn;
            float h  = o * tanh_(cn);
            hlast[i] = h;
            __stcg(&orow[(size_t)(r0 + i) * HID + j], h);
        }

        // Per-ry 32-CTA scoped-atomic barrier (no fences, no sleep).
        if (t < T_STEPS - 1) {
            __syncthreads();
            if (tid == 0) {
                unsigned old = atom_add_acqrel(barc, 1u);
                if (old == 31u) {
                    *barc = 0;                       // ordered by release below
                    red_add_release(barg, 1u);
                } else {
                    unsigned target = (unsigned)(t + 1);
                    while (ld_acquire(barg) < target) { }
                }
            }
            __syncthreads();
        }
    }

    if (write_final) {
        size_t base = (size_t)T_STEPS * BH;
        #pragma unroll
        for (int i = 0; i < 2; i++) {
            out[base + (size_t)(r0 + i) * HID + j]      = hlast[i];
            out[base + BH + (size_t)(r0 + i) * HID + j] = creg[i];
        }
    }
}

// ---------------------------------------------------------------------------
extern "C" void kernel_launch(void* const* d_in, const int* in_sizes, int n_in,
                              void* d_out, int out_size)
{
    const float* x  = (const float*)d_in[0];
    const float* Wf = (const float*)d_in[1];
    const float* bf = (const float*)d_in[2];
    const float* Wi = (const float*)d_in[3];
    const float* bi = (const float*)d_in[4];
    const float* Wg = (const float*)d_in[5];
    const float* bg = (const float*)d_in[6];
    const float* Wo = (const float*)d_in[7];
    const float* bo = (const float*)d_in[8];
    float* out = (float*)d_out;

    static int attr_set = 0;
    if (!attr_set) {
        cudaFuncSetAttribute(lstm_persist,
                             cudaFuncAttributeMaxDynamicSharedMemorySize,
                             SMEM_PERSIST);
        attr_set = 1;
    }

    dim3 g1(NG / BN, M_ALL / BM);
    sgemm_x<<<g1, 256>>>(x, Wf, Wi, Wg, Wo, bf, bi, bg, bo);

    long long need = (long long)T_STEPS * BH + 2LL * BH;
    int wf = ((long long)out_size >= need) ? 1 : 0;
    lstm_persist<<<dim3(32, 4), 256, SMEM_PERSIST>>>(out, wf, Wf, Wi, Wg, Wo);
}

// round 10
// speedup vs baseline: 1.2227x; 1.1995x over previous
#include <cuda_runtime.h>
#include <math.h>

// LSTM T=512, B=128, D_in=H=512.  Two kernels:
//  sgemm_x:      Gx[65536 x 2048] = X @ Wx + bias (gate-interleaved, FFMA2).
//  lstm_persist: 128 co-resident CTAs x 256 thr, 512 steps.
//                Split-K within the CTA: two 128-thread groups each compute
//                256 of the 512 k for the same 32x64 tile (4r x 4c microtile,
//                register double-buffered), combine via smem, fused epilogue.

#define T_STEPS 512
#define BATCH   128
#define HID     512
#define DIN     512
#define NG      2048
#define M_ALL   (T_STEPS * BATCH)
#define BH      (BATCH * HID)

__device__ float g_Gx[(size_t)M_ALL * NG];          // 512 MB scratch
__device__ unsigned int g_bar[256];                 // [ry*64]=count, [ry*64+32]=gen

typedef unsigned long long ull;
union F4U { float4 f; ull u[2]; float s[4]; };

__device__ __forceinline__ void ffma2(ull& d, ull a, ull b) {
    asm("fma.rn.f32x2 %0, %1, %2, %0;" : "+l"(d) : "l"(a), "l"(b));
}
__device__ __forceinline__ ull dup2(float x) {
    ull r; asm("mov.b64 %0, {%1, %1};" : "=l"(r) : "f"(x)); return r;
}
__device__ __forceinline__ void unpk(ull v, float& lo, float& hi) {
    asm("mov.b64 {%0, %1}, %2;" : "=f"(lo), "=f"(hi) : "l"(v));
}
__device__ __forceinline__ float sigm(float x) {
    return __fdividef(1.0f, 1.0f + __expf(-x));
}
__device__ __forceinline__ float tanh_(float x) {
    return __fdividef(2.0f, 1.0f + __expf(-2.0f * x)) - 1.0f;
}
__device__ __forceinline__ unsigned atom_add_acqrel(unsigned* p, unsigned v) {
    unsigned old;
    asm volatile("atom.acq_rel.gpu.global.add.u32 %0, [%1], %2;"
                 : "=r"(old) : "l"(p), "r"(v) : "memory");
    return old;
}
__device__ __forceinline__ void red_add_release(unsigned* p, unsigned v) {
    asm volatile("red.release.gpu.global.add.u32 [%0], %1;"
                 :: "l"(p), "r"(v) : "memory");
}
__device__ __forceinline__ unsigned ld_acquire(const unsigned* p) {
    unsigned v;
    asm volatile("ld.acquire.gpu.global.u32 %0, [%1];"
                 : "=r"(v) : "l"(p) : "memory");
    return v;
}
__device__ __forceinline__ void barx(int id, int cnt) {
    asm volatile("bar.sync %0, %1;" :: "r"(id), "r"(cnt) : "memory");
}

// ---------------------------------------------------------------------------
// Phase 1: Gx = X @ Wx + bias.  128x128 tile, BK=16, 256 thr, 8x8 microtile,
// FFMA2, register double-buffering, gate-interleaved B gather.
// ---------------------------------------------------------------------------
#define BM 128
#define BN 128
#define BK 16

__global__ __launch_bounds__(256) void sgemm_x(
    const float* __restrict__ X,
    const float* __restrict__ Wf, const float* __restrict__ Wi,
    const float* __restrict__ Wg, const float* __restrict__ Wo,
    const float* __restrict__ bfp, const float* __restrict__ bip,
    const float* __restrict__ bgp, const float* __restrict__ bop)
{
    __shared__ float As[BK][BM + 4];
    __shared__ float Bs[BK][BN];

    const int tid  = threadIdx.x;
    const int tx   = tid & 15;
    const int ty   = tid >> 4;
    const int row0 = blockIdx.y * BM;
    const int col0 = blockIdx.x * BN;

    if (blockIdx.x == 0 && blockIdx.y == 0 && tid < 8)
        g_bar[(tid & 3) * 64 + (tid >> 2) * 32] = 0;   // reset persist barriers

    const int ar0 = tid >> 2, ak0 = (tid & 3) << 2;
    const int ar1 = (tid + 256) >> 2, ak1 = ((tid + 256) & 3) << 2;
    const int br0 = tid >> 5, br1 = (tid + 256) >> 5;
    const int jj  = (col0 >> 2) + (tid & 31);
    const int bc  = (tid & 31) << 2;

    float4 pa0, pa1;
    float  pb0[4], pb1[4];

    pa0 = *(const float4*)(X + (size_t)(row0 + ar0) * DIN + ak0);
    pa1 = *(const float4*)(X + (size_t)(row0 + ar1) * DIN + ak1);
    {
        size_t o0 = (size_t)br0 * HID + jj, o1 = (size_t)br1 * HID + jj;
        pb0[0] = Wf[o0]; pb0[1] = Wi[o0]; pb0[2] = Wg[o0]; pb0[3] = Wo[o0];
        pb1[0] = Wf[o1]; pb1[1] = Wi[o1]; pb1[2] = Wg[o1]; pb1[3] = Wo[o1];
    }
    As[ak0 + 0][ar0] = pa0.x; As[ak0 + 1][ar0] = pa0.y;
    As[ak0 + 2][ar0] = pa0.z; As[ak0 + 3][ar0] = pa0.w;
    As[ak1 + 0][ar1] = pa1.x; As[ak1 + 1][ar1] = pa1.y;
    As[ak1 + 2][ar1] = pa1.z; As[ak1 + 3][ar1] = pa1.w;
    Bs[br0][bc + 0] = pb0[0]; Bs[br0][bc + 1] = pb0[1];
    Bs[br0][bc + 2] = pb0[2]; Bs[br0][bc + 3] = pb0[3];
    Bs[br1][bc + 0] = pb1[0]; Bs[br1][bc + 1] = pb1[1];
    Bs[br1][bc + 2] = pb1[2]; Bs[br1][bc + 3] = pb1[3];
    __syncthreads();

    ull acc[8][4];
    #pragma unroll
    for (int i = 0; i < 8; i++)
        #pragma unroll
        for (int j = 0; j < 4; j++) acc[i][j] = 0ull;

    for (int k0 = 0; k0 < DIN; k0 += BK) {
        const bool more = (k0 + BK) < DIN;
        if (more) {
            int kn = k0 + BK;
            pa0 = *(const float4*)(X + (size_t)(row0 + ar0) * DIN + kn + ak0);
            pa1 = *(const float4*)(X + (size_t)(row0 + ar1) * DIN + kn + ak1);
            size_t o0 = (size_t)(kn + br0) * HID + jj;
            size_t o1 = (size_t)(kn + br1) * HID + jj;
            pb0[0] = Wf[o0]; pb0[1] = Wi[o0]; pb0[2] = Wg[o0]; pb0[3] = Wo[o0];
            pb1[0] = Wf[o1]; pb1[1] = Wi[o1]; pb1[2] = Wg[o1]; pb1[3] = Wo[o1];
        }

        #pragma unroll
        for (int k = 0; k < BK; k++) {
            F4U aA, aB, bA, bB;
            aA.f = *(float4*)&As[k][ty * 8];
            aB.f = *(float4*)&As[k][ty * 8 + 4];
            bA.f = *(float4*)&Bs[k][tx * 8];
            bB.f = *(float4*)&Bs[k][tx * 8 + 4];
            ull ad[8];
            #pragma unroll
            for (int i = 0; i < 4; i++) { ad[i] = dup2(aA.s[i]); ad[4 + i] = dup2(aB.s[i]); }
            #pragma unroll
            for (int i = 0; i < 8; i++) {
                ffma2(acc[i][0], ad[i], bA.u[0]);
                ffma2(acc[i][1], ad[i], bA.u[1]);
                ffma2(acc[i][2], ad[i], bB.u[0]);
                ffma2(acc[i][3], ad[i], bB.u[1]);
            }
        }
        __syncthreads();
        if (more) {
            As[ak0 + 0][ar0] = pa0.x; As[ak0 + 1][ar0] = pa0.y;
            As[ak0 + 2][ar0] = pa0.z; As[ak0 + 3][ar0] = pa0.w;
            As[ak1 + 0][ar1] = pa1.x; As[ak1 + 1][ar1] = pa1.y;
            As[ak1 + 2][ar1] = pa1.z; As[ak1 + 3][ar1] = pa1.w;
            Bs[br0][bc + 0] = pb0[0]; Bs[br0][bc + 1] = pb0[1];
            Bs[br0][bc + 2] = pb0[2]; Bs[br0][bc + 3] = pb0[3];
            Bs[br1][bc + 0] = pb1[0]; Bs[br1][bc + 1] = pb1[1];
            Bs[br1][bc + 2] = pb1[2]; Bs[br1][bc + 3] = pb1[3];
            __syncthreads();
        }
    }

    const int ju0 = (col0 + tx * 8) >> 2;
    float b8[8];
    b8[0] = bfp[ju0];     b8[1] = bip[ju0];     b8[2] = bgp[ju0];     b8[3] = bop[ju0];
    b8[4] = bfp[ju0 + 1]; b8[5] = bip[ju0 + 1]; b8[6] = bgp[ju0 + 1]; b8[7] = bop[ju0 + 1];

    #pragma unroll
    for (int i = 0; i < 8; i++) {
        int r = row0 + ty * 8 + i;
        int c = col0 + tx * 8;
        float o[8];
        unpk(acc[i][0], o[0], o[1]);
        unpk(acc[i][1], o[2], o[3]);
        unpk(acc[i][2], o[4], o[5]);
        unpk(acc[i][3], o[6], o[7]);
        float4 v0 = make_float4(o[0] + b8[0], o[1] + b8[1], o[2] + b8[2], o[3] + b8[3]);
        float4 v1 = make_float4(o[4] + b8[4], o[5] + b8[5], o[6] + b8[6], o[7] + b8[7]);
        __stcs((float4*)(g_Gx + (size_t)r * NG + c),     v0);
        __stcs((float4*)(g_Gx + (size_t)r * NG + c + 4), v1);
    }
}

// ---------------------------------------------------------------------------
// Phase 2: persistent kernel. Grid (32 cx, 4 ry) = 128 CTAs, 256 threads.
// CTA(cx,ry): cols [cx*64, +64) = 16 hidden units x 4 gates, rows [ry*32, +32).
// Split-K: group kg = tid>>7 computes k in [kg*256, kg*256+256).
// Within group: tx = unit 0..15 (4 gate cols), ty = row quad 0..7 (4 rows).
// Group 1 writes partials to smem; group 0 combines + fused LSTM epilogue.
// ---------------------------------------------------------------------------
#define HSTRIDE 516
#define SMEM_PERSIST ((512 * 64 + 32 * HSTRIDE) * 4)

__global__ __launch_bounds__(256, 1) void lstm_persist(
    float* __restrict__ out, int write_final,
    const float* __restrict__ Wf, const float* __restrict__ Wi,
    const float* __restrict__ Wg, const float* __restrict__ Wo)
{
    extern __shared__ float smem[];
    float*  Ws  = smem;              // [512][64] gate-interleaved Wh slice
    float*  Hs  = smem + 512 * 64;   // [32][HSTRIDE] h staging
    float4* Cb  = (float4*)Hs;       // combine buffer overlay: [4][128] float4

    const int tid   = threadIdx.x;
    const int tg    = tid & 127;
    const int kg    = tid >> 7;            // 0,1: k half
    const int tx    = tg & 15;             // unit within CTA cols
    const int ty    = tg >> 4;             // row quad 0..7
    const int tx4   = tx << 2;
    const int col0  = blockIdx.x * 64;
    const int ry    = blockIdx.y;
    const int row_base = ry * 32;
    const int j     = (col0 >> 2) + tx;
    const int r0    = row_base + ty * 4;
    const int kbase = kg * 256;

    unsigned* barc = &g_bar[ry * 64];
    unsigned* barg = &g_bar[ry * 64 + 32];

    // Preload gate-interleaved Wh slice into smem (once, gathered).
    {
        const int jbase = col0 >> 2;
        #pragma unroll
        for (int g = 0; g < 4; g++) {
            const float* Wp = (g == 0) ? Wf : (g == 1) ? Wi : (g == 2) ? Wg : Wo;
            for (int p = 0; p < 32; p++) {
                int idx = tid + p * 256;
                int k = idx >> 4, u = idx & 15;
                Ws[k * 64 + u * 4 + g] = Wp[(size_t)(DIN + k) * HID + jbase + u];
            }
        }
    }
    __syncthreads();

    float creg[4]  = {0.f, 0.f, 0.f, 0.f};
    float hlast[4] = {0.f, 0.f, 0.f, 0.f};

    // Per-group fill indices: 32 rows x 256 floats (own k-half).
    const int fhr = tg >> 2;        // 0..31
    const int fcb = tg & 3;         // 0..3

    // Row pointers into own k-half.
    const float* hrow[4];
    #pragma unroll
    for (int i = 0; i < 4; i++) hrow[i] = &Hs[(ty * 4 + i) * HSTRIDE + kbase];
    const float* wsp = Ws + (size_t)kbase * 64 + tx4;

    for (int t = 0; t < T_STEPS; t++) {
        // Group 0: prefetch this step's Gx quads (epilogue-only).
        float4 gx[4];
        if (kg == 0) {
            const float4* gxp = (const float4*)(g_Gx + ((size_t)t * BATCH + r0) * NG + col0 + tx4);
            #pragma unroll
            for (int i = 0; i < 4; i++) gx[i] = __ldcs(gxp + (size_t)i * (NG / 4));
        }

        ull acc[4][2];
        #pragma unroll
        for (int i = 0; i < 4; i++) { acc[i][0] = 0ull; acc[i][1] = 0ull; }

        if (t > 0) {
            // Each group fills its own k-half of Hs (32 rows x 256 floats).
            const float* hp = out + (size_t)(t - 1) * BH + kbase;
            #pragma unroll
            for (int i = 0; i < 16; i++) {
                int c4 = (fcb + i * 4) << 2;         // 0..252
                float4 v = __ldcg((const float4*)(hp + (size_t)(row_base + fhr) * HID + c4));
                *(float4*)&Hs[fhr * HSTRIDE + kbase + c4] = v;
            }
            barx(1 + kg, 128);                        // per-group fill sync

            // GEMM over own 256-k half, register double-buffered.
            F4U ha[4], wb[4], han[4], wbn[4];
            #pragma unroll
            for (int i = 0; i < 4; i++) ha[i].f = *(const float4*)(hrow[i]);
            #pragma unroll
            for (int kk = 0; kk < 4; kk++) wb[kk].f = *(const float4*)(wsp + kk * 64);

            #pragma unroll 2
            for (int g4 = 0; g4 < 64; g4++) {
                if (g4 < 63) {
                    int kn = (g4 + 1) * 4;
                    #pragma unroll
                    for (int i = 0; i < 4; i++) han[i].f = *(const float4*)(hrow[i] + kn);
                    #pragma unroll
                    for (int kk = 0; kk < 4; kk++) wbn[kk].f = *(const float4*)(wsp + (kn + kk) * 64);
                }
                #pragma unroll
                for (int kk = 0; kk < 4; kk++) {
                    ull w0 = wb[kk].u[0], w1 = wb[kk].u[1];
                    #pragma unroll
                    for (int i = 0; i < 4; i++) {
                        ull d = dup2(ha[i].s[kk]);
                        ffma2(acc[i][0], d, w0);
                        ffma2(acc[i][1], d, w1);
                    }
                }
                #pragma unroll
                for (int i = 0; i < 4; i++) ha[i] = han[i];
                #pragma unroll
                for (int kk = 0; kk < 4; kk++) wb[kk] = wbn[kk];
            }

            // Combine: group 1 -> smem -> group 0.
            __syncthreads();
            if (kg == 1) {
                #pragma unroll
                for (int i = 0; i < 4; i++) {
                    F4U p; p.u[0] = acc[i][0]; p.u[1] = acc[i][1];
                    Cb[i * 128 + tg] = p.f;
                }
            }
            __syncthreads();
        }

        // Fused LSTM epilogue (group 0 only): unit j, rows r0..r0+3.
        if (kg == 0) {
            float* orow = out + (size_t)t * BH;
            #pragma unroll
            for (int i = 0; i < 4; i++) {
                float pf, pi, pg, po;
                unpk(acc[i][0], pf, pi);
                unpk(acc[i][1], pg, po);
                if (t > 0) {
                    F4U p; p.f = Cb[i * 128 + tg];
                    pf += p.s[0]; pi += p.s[1]; pg += p.s[2]; po += p.s[3];
                }
                float f  = sigm(pf + gx[i].x);
                float ii = sigm(pi + gx[i].y);
                float g  = tanh_(pg + gx[i].z);
                float o  = sigm(po + gx[i].w);
                float cn = f * creg[i] + ii * g;
                creg[i]  = cn;
                float h  = o * tanh_(cn);
                hlast[i] = h;
                __stcg(&orow[(size_t)(r0 + i) * HID + j], h);
            }
        }

        // Per-ry 32-CTA scoped-atomic barrier.
        if (t < T_STEPS - 1) {
            __syncthreads();
            if (tid == 0) {
                unsigned old = atom_add_acqrel(barc, 1u);
                if (old == 31u) {
                    *barc = 0;
                    red_add_release(barg, 1u);
                } else {
                    unsigned target = (unsigned)(t + 1);
                    while (ld_acquire(barg) < target) { }
                }
            }
            __syncthreads();
        }
    }

    if (write_final && kg == 0) {
        size_t base = (size_t)T_STEPS * BH;
        #pragma unroll
        for (int i = 0; i < 4; i++) {
            out[base + (size_t)(r0 + i) * HID + j]      = hlast[i];
            out[base + BH + (size_t)(r0 + i) * HID + j] = creg[i];
        }
    }
}

// ---------------------------------------------------------------------------
extern "C" void kernel_launch(void* const* d_in, const int* in_sizes, int n_in,
                              void* d_out, int out_size)
{
    const float* x  = (const float*)d_in[0];
    const float* Wf = (const float*)d_in[1];
    const float* bf = (const float*)d_in[2];
    const float* Wi = (const float*)d_in[3];
    const float* bi = (const float*)d_in[4];
    const float* Wg = (const float*)d_in[5];
    const float* bg = (const float*)d_in[6];
    const float* Wo = (const float*)d_in[7];
    const float* bo = (const float*)d_in[8];
    float* out = (float*)d_out;

    static int attr_set = 0;
    if (!attr_set) {
        cudaFuncSetAttribute(lstm_persist,
                             cudaFuncAttributeMaxDynamicSharedMemorySize,
                             SMEM_PERSIST);
        attr_set = 1;
    }

    dim3 g1(NG / BN, M_ALL / BM);
    sgemm_x<<<g1, 256>>>(x, Wf, Wi, Wg, Wo, bf, bi, bg, bo);

    long long need = (long long)T_STEPS * BH + 2LL * BH;
    int wf = ((long long)out_size >= need) ? 1 : 0;
    lstm_persist<<<dim3(32, 4), 256, SMEM_PERSIST>>>(out, wf, Wf, Wi, Wg, Wo);
}

// round 11
// speedup vs baseline: 1.2664x; 1.0358x over previous
#include <cuda_runtime.h>
#include <math.h>

// LSTM T=512, B=128, D_in=H=512.  Two kernels:
//  sgemm_x:      Gx[65536 x 2048] = X @ Wx + bias (gate-interleaved, FFMA2).
//                Also resets the dataflow flags.
//  lstm_persist: 128 free-running CTAs x 256 thr, 512 steps, NO global barrier:
//                per-producer generation flags (release/acquire) gate the h fill.
//                Split-K two groups; epilogue split across groups (2 rows each).

#define T_STEPS 512
#define BATCH   128
#define HID     512
#define DIN     512
#define NG      2048
#define M_ALL   (T_STEPS * BATCH)
#define BH      (BATCH * HID)

__device__ float g_Gx[(size_t)M_ALL * NG];          // 512 MB scratch
__device__ unsigned int g_flag[4096];               // flag[(ry*32+cx)*32]: steps published

typedef unsigned long long ull;
union F4U { float4 f; ull u[2]; float s[4]; };

__device__ __forceinline__ void ffma2(ull& d, ull a, ull b) {
    asm("fma.rn.f32x2 %0, %1, %2, %0;" : "+l"(d) : "l"(a), "l"(b));
}
__device__ __forceinline__ ull dup2(float x) {
    ull r; asm("mov.b64 %0, {%1, %1};" : "=l"(r) : "f"(x)); return r;
}
__device__ __forceinline__ void unpk(ull v, float& lo, float& hi) {
    asm("mov.b64 {%0, %1}, %2;" : "=f"(lo), "=f"(hi) : "l"(v));
}
__device__ __forceinline__ float sigm(float x) {
    return __fdividef(1.0f, 1.0f + __expf(-x));
}
__device__ __forceinline__ float tanh_(float x) {
    return __fdividef(2.0f, 1.0f + __expf(-2.0f * x)) - 1.0f;
}
__device__ __forceinline__ unsigned ld_acquire(const unsigned* p) {
    unsigned v;
    asm volatile("ld.acquire.gpu.global.u32 %0, [%1];"
                 : "=r"(v) : "l"(p) : "memory");
    return v;
}
__device__ __forceinline__ void st_release(unsigned* p, unsigned v) {
    asm volatile("st.release.gpu.global.u32 [%0], %1;"
                 :: "l"(p), "r"(v) : "memory");
}
__device__ __forceinline__ void barx(int id, int cnt) {
    asm volatile("bar.sync %0, %1;" :: "r"(id), "r"(cnt) : "memory");
}

// ---------------------------------------------------------------------------
// Phase 1: Gx = X @ Wx + bias.  128x128 tile, BK=16, 256 thr, 8x8 microtile,
// FFMA2, register double-buffering, gate-interleaved B gather.
// ---------------------------------------------------------------------------
#define BM 128
#define BN 128
#define BK 16

__global__ __launch_bounds__(256) void sgemm_x(
    const float* __restrict__ X,
    const float* __restrict__ Wf, const float* __restrict__ Wi,
    const float* __restrict__ Wg, const float* __restrict__ Wo,
    const float* __restrict__ bfp, const float* __restrict__ bip,
    const float* __restrict__ bgp, const float* __restrict__ bop)
{
    __shared__ float As[BK][BM + 4];
    __shared__ float Bs[BK][BN];

    const int tid  = threadIdx.x;
    const int tx   = tid & 15;
    const int ty   = tid >> 4;
    const int row0 = blockIdx.y * BM;
    const int col0 = blockIdx.x * BN;

    if (blockIdx.x == 0 && blockIdx.y == 0 && tid < 128)
        g_flag[tid * 32] = 0;                        // reset dataflow flags

    const int ar0 = tid >> 2, ak0 = (tid & 3) << 2;
    const int ar1 = (tid + 256) >> 2, ak1 = ((tid + 256) & 3) << 2;
    const int br0 = tid >> 5, br1 = (tid + 256) >> 5;
    const int jj  = (col0 >> 2) + (tid & 31);
    const int bc  = (tid & 31) << 2;

    float4 pa0, pa1;
    float  pb0[4], pb1[4];

    pa0 = *(const float4*)(X + (size_t)(row0 + ar0) * DIN + ak0);
    pa1 = *(const float4*)(X + (size_t)(row0 + ar1) * DIN + ak1);
    {
        size_t o0 = (size_t)br0 * HID + jj, o1 = (size_t)br1 * HID + jj;
        pb0[0] = Wf[o0]; pb0[1] = Wi[o0]; pb0[2] = Wg[o0]; pb0[3] = Wo[o0];
        pb1[0] = Wf[o1]; pb1[1] = Wi[o1]; pb1[2] = Wg[o1]; pb1[3] = Wo[o1];
    }
    As[ak0 + 0][ar0] = pa0.x; As[ak0 + 1][ar0] = pa0.y;
    As[ak0 + 2][ar0] = pa0.z; As[ak0 + 3][ar0] = pa0.w;
    As[ak1 + 0][ar1] = pa1.x; As[ak1 + 1][ar1] = pa1.y;
    As[ak1 + 2][ar1] = pa1.z; As[ak1 + 3][ar1] = pa1.w;
    Bs[br0][bc + 0] = pb0[0]; Bs[br0][bc + 1] = pb0[1];
    Bs[br0][bc + 2] = pb0[2]; Bs[br0][bc + 3] = pb0[3];
    Bs[br1][bc + 0] = pb1[0]; Bs[br1][bc + 1] = pb1[1];
    Bs[br1][bc + 2] = pb1[2]; Bs[br1][bc + 3] = pb1[3];
    __syncthreads();

    ull acc[8][4];
    #pragma unroll
    for (int i = 0; i < 8; i++)
        #pragma unroll
        for (int j = 0; j < 4; j++) acc[i][j] = 0ull;

    for (int k0 = 0; k0 < DIN; k0 += BK) {
        const bool more = (k0 + BK) < DIN;
        if (more) {
            int kn = k0 + BK;
            pa0 = *(const float4*)(X + (size_t)(row0 + ar0) * DIN + kn + ak0);
            pa1 = *(const float4*)(X + (size_t)(row0 + ar1) * DIN + kn + ak1);
            size_t o0 = (size_t)(kn + br0) * HID + jj;
            size_t o1 = (size_t)(kn + br1) * HID + jj;
            pb0[0] = Wf[o0]; pb0[1] = Wi[o0]; pb0[2] = Wg[o0]; pb0[3] = Wo[o0];
            pb1[0] = Wf[o1]; pb1[1] = Wi[o1]; pb1[2] = Wg[o1]; pb1[3] = Wo[o1];
        }

        #pragma unroll
        for (int k = 0; k < BK; k++) {
            F4U aA, aB, bA, bB;
            aA.f = *(float4*)&As[k][ty * 8];
            aB.f = *(float4*)&As[k][ty * 8 + 4];
            bA.f = *(float4*)&Bs[k][tx * 8];
            bB.f = *(float4*)&Bs[k][tx * 8 + 4];
            ull ad[8];
            #pragma unroll
            for (int i = 0; i < 4; i++) { ad[i] = dup2(aA.s[i]); ad[4 + i] = dup2(aB.s[i]); }
            #pragma unroll
            for (int i = 0; i < 8; i++) {
                ffma2(acc[i][0], ad[i], bA.u[0]);
                ffma2(acc[i][1], ad[i], bA.u[1]);
                ffma2(acc[i][2], ad[i], bB.u[0]);
                ffma2(acc[i][3], ad[i], bB.u[1]);
            }
        }
        __syncthreads();
        if (more) {
            As[ak0 + 0][ar0] = pa0.x; As[ak0 + 1][ar0] = pa0.y;
            As[ak0 + 2][ar0] = pa0.z; As[ak0 + 3][ar0] = pa0.w;
            As[ak1 + 0][ar1] = pa1.x; As[ak1 + 1][ar1] = pa1.y;
            As[ak1 + 2][ar1] = pa1.z; As[ak1 + 3][ar1] = pa1.w;
            Bs[br0][bc + 0] = pb0[0]; Bs[br0][bc + 1] = pb0[1];
            Bs[br0][bc + 2] = pb0[2]; Bs[br0][bc + 3] = pb0[3];
            Bs[br1][bc + 0] = pb1[0]; Bs[br1][bc + 1] = pb1[1];
            Bs[br1][bc + 2] = pb1[2]; Bs[br1][bc + 3] = pb1[3];
            __syncthreads();
        }
    }

    const int ju0 = (col0 + tx * 8) >> 2;
    float b8[8];
    b8[0] = bfp[ju0];     b8[1] = bip[ju0];     b8[2] = bgp[ju0];     b8[3] = bop[ju0];
    b8[4] = bfp[ju0 + 1]; b8[5] = bip[ju0 + 1]; b8[6] = bgp[ju0 + 1]; b8[7] = bop[ju0 + 1];

    #pragma unroll
    for (int i = 0; i < 8; i++) {
        int r = row0 + ty * 8 + i;
        int c = col0 + tx * 8;
        float o[8];
        unpk(acc[i][0], o[0], o[1]);
        unpk(acc[i][1], o[2], o[3]);
        unpk(acc[i][2], o[4], o[5]);
        unpk(acc[i][3], o[6], o[7]);
        float4 v0 = make_float4(o[0] + b8[0], o[1] + b8[1], o[2] + b8[2], o[3] + b8[3]);
        float4 v1 = make_float4(o[4] + b8[4], o[5] + b8[5], o[6] + b8[6], o[7] + b8[7]);
        __stcs((float4*)(g_Gx + (size_t)r * NG + c),     v0);
        __stcs((float4*)(g_Gx + (size_t)r * NG + c + 4), v1);
    }
}

// ---------------------------------------------------------------------------
// Phase 2: persistent free-running kernel. Grid (32 cx, 4 ry) = 128 CTAs,
// 256 threads. CTA(cx,ry): gate cols [cx*64,+64) = units [16cx,+16),
// rows [ry*32,+32). Split-K: group kg = tid>>7 computes k in [kg*256,+256).
// Sync: producer CTA p publishes h cols [16p,+16) for its rows each step and
// release-stores flag[(ry,p)] = t+1. Consumer group kg gates its fill on the
// 16 producer flags covering its k-half (one flag per lane, parallel poll).
// Epilogue split: group kg owns rows ty*4 + {2kg, 2kg+1}; partials for the
// other group's rows exchanged via smem.
// ---------------------------------------------------------------------------
#define HSTRIDE 516
#define SMEM_PERSIST ((512 * 64 + 32 * HSTRIDE) * 4)

__global__ __launch_bounds__(256, 1) void lstm_persist(
    float* __restrict__ out, int write_final,
    const float* __restrict__ Wf, const float* __restrict__ Wi,
    const float* __restrict__ Wg, const float* __restrict__ Wo)
{
    extern __shared__ float smem[];
    float*  Ws  = smem;              // [512][64] gate-interleaved Wh slice
    float*  Hs  = smem + 512 * 64;   // [32][HSTRIDE] h staging
    float4* Cb  = (float4*)Hs;       // combine buffer overlay: [4][128] float4

    const int tid   = threadIdx.x;
    const int lane  = tid & 31;
    const int tg    = tid & 127;
    const int kg    = tid >> 7;            // 0,1: k half
    const int tx    = tg & 15;             // unit within CTA cols
    const int ty    = tg >> 4;             // row quad 0..7
    const int tx4   = tx << 2;
    const int cx    = blockIdx.x;
    const int col0  = cx * 64;
    const int ry    = blockIdx.y;
    const int row_base = ry * 32;
    const int j     = (col0 >> 2) + tx;
    const int r0    = row_base + ty * 4;
    const int kbase = kg * 256;
    const int io    = kg * 2;              // first owned epilogue row index

    unsigned* fme = &g_flag[(ry * 32 + cx) * 32];
    const unsigned* fwatch = &g_flag[(ry * 32 + kg * 16 + (lane & 15)) * 32];

    // Preload gate-interleaved Wh slice into smem (once, gathered).
    {
        const int jbase = col0 >> 2;
        #pragma unroll
        for (int g = 0; g < 4; g++) {
            const float* Wp = (g == 0) ? Wf : (g == 1) ? Wi : (g == 2) ? Wg : Wo;
            for (int p = 0; p < 32; p++) {
                int idx = tid + p * 256;
                int k = idx >> 4, u = idx & 15;
                Ws[k * 64 + u * 4 + g] = Wp[(size_t)(DIN + k) * HID + jbase + u];
            }
        }
    }
    __syncthreads();

    float creg[2]  = {0.f, 0.f};
    float hlast[2] = {0.f, 0.f};

    const int frow = tg >> 2;       // fill: row 0..31
    const int fc4  = (tg & 3) << 2; // fill: float offset within 16-col chunk

    const float* hrow[4];
    #pragma unroll
    for (int i = 0; i < 4; i++) hrow[i] = &Hs[(ty * 4 + i) * HSTRIDE + kbase];
    const float* wsp = Ws + (size_t)kbase * 64 + tx4;

    for (int t = 0; t < T_STEPS; t++) {
        // Prefetch this step's Gx quads for the 2 owned rows.
        float4 gx[2];
        {
            const float4* gxp = (const float4*)(g_Gx + ((size_t)t * BATCH + r0 + io) * NG + col0 + tx4);
            gx[0] = __ldcs(gxp);
            gx[1] = __ldcs(gxp + NG / 4);
        }

        ull acc[4][2];
        #pragma unroll
        for (int i = 0; i < 4; i++) { acc[i][0] = 0ull; acc[i][1] = 0ull; }

        if (t > 0) {
            // Parallel poll: lane L watches producer kg*16 + (L&15).
            while (ld_acquire(fwatch) < (unsigned)t) { }
            barx(1 + kg, 128);   // group-wide happens-before for all 16 flags

            // Bulk fill: 16 chunks (32 rows x 16 cols each) of own k-half.
            const float* hp = out + (size_t)(t - 1) * BH + (size_t)(row_base + frow) * HID;
            #pragma unroll
            for (int cc = 0; cc < 16; cc++) {
                int kc = (kg * 16 + cc) * 16 + fc4;
                float4 v = __ldcg((const float4*)(hp + kc));
                *(float4*)&Hs[frow * HSTRIDE + kc] = v;
            }
            barx(1 + kg, 128);

            // GEMM over own 256-k half, register double-buffered.
            F4U ha[4], wb[4], han[4], wbn[4];
            #pragma unroll
            for (int i = 0; i < 4; i++) ha[i].f = *(const float4*)(hrow[i]);
            #pragma unroll
            for (int kk = 0; kk < 4; kk++) wb[kk].f = *(const float4*)(wsp + kk * 64);

            #pragma unroll 2
            for (int g4 = 0; g4 < 64; g4++) {
                if (g4 < 63) {
                    int kn = (g4 + 1) * 4;
                    #pragma unroll
                    for (int i = 0; i < 4; i++) han[i].f = *(const float4*)(hrow[i] + kn);
                    #pragma unroll
                    for (int kk = 0; kk < 4; kk++) wbn[kk].f = *(const float4*)(wsp + (kn + kk) * 64);
                }
                #pragma unroll
                for (int kk = 0; kk < 4; kk++) {
                    ull w0 = wb[kk].u[0], w1 = wb[kk].u[1];
                    #pragma unroll
                    for (int i = 0; i < 4; i++) {
                        ull d = dup2(ha[i].s[kk]);
                        ffma2(acc[i][0], d, w0);
                        ffma2(acc[i][1], d, w1);
                    }
                }
                #pragma unroll
                for (int i = 0; i < 4; i++) ha[i] = han[i];
                #pragma unroll
                for (int kk = 0; kk < 4; kk++) wb[kk] = wbn[kk];
            }

            // Symmetric partial exchange: write the 2 rows the OTHER group owns.
            __syncthreads();
            {
                int iw0 = 2 - 2 * kg;
                #pragma unroll
                for (int ii = 0; ii < 2; ii++) {
                    int i = iw0 + ii;
                    F4U p; p.u[0] = acc[i][0]; p.u[1] = acc[i][1];
                    Cb[i * 128 + tg] = p.f;
                }
            }
            __syncthreads();
        }

        // Fused LSTM epilogue: both groups, 2 owned rows each.
        float* orow = out + (size_t)t * BH;
        #pragma unroll
        for (int ii = 0; ii < 2; ii++) {
            int i = io + ii;
            float pf, pi, pg, po;
            unpk(acc[i][0], pf, pi);
            unpk(acc[i][1], pg, po);
            if (t > 0) {
                F4U p; p.f = Cb[i * 128 + tg];
                pf += p.s[0]; pi += p.s[1]; pg += p.s[2]; po += p.s[3];
            }
            float f  = sigm(pf + gx[ii].x);
            float iv = sigm(pi + gx[ii].y);
            float g  = tanh_(pg + gx[ii].z);
            float o  = sigm(po + gx[ii].w);
            float cn = f * creg[ii] + iv * g;
            creg[ii] = cn;
            float h  = o * tanh_(cn);
            hlast[ii] = h;
            __stcg(&orow[(size_t)(r0 + i) * HID + j], h);
        }

        // Publish h_t: one release-store flag per producer CTA.
        if (t < T_STEPS - 1) {
            __syncthreads();
            if (tid == 0) st_release(fme, (unsigned)(t + 1));
        }
    }

    if (write_final) {
        size_t base = (size_t)T_STEPS * BH;
        #pragma unroll
        for (int ii = 0; ii < 2; ii++) {
            out[base + (size_t)(r0 + io + ii) * HID + j]      = hlast[ii];
            out[base + BH + (size_t)(r0 + io + ii) * HID + j] = creg[ii];
        }
    }
}

// ---------------------------------------------------------------------------
extern "C" void kernel_launch(void* const* d_in, const int* in_sizes, int n_in,
                              void* d_out, int out_size)
{
    const float* x  = (const float*)d_in[0];
    const float* Wf = (const float*)d_in[1];
    const float* bf = (const float*)d_in[2];
    const float* Wi = (const float*)d_in[3];
    const float* bi = (const float*)d_in[4];
    const float* Wg = (const float*)d_in[5];
    const float* bg = (const float*)d_in[6];
    const float* Wo = (const float*)d_in[7];
    const float* bo = (const float*)d_in[8];
    float* out = (float*)d_out;

    static int attr_set = 0;
    if (!attr_set) {
        cudaFuncSetAttribute(lstm_persist,
                             cudaFuncAttributeMaxDynamicSharedMemorySize,
                             SMEM_PERSIST);
        attr_set = 1;
    }

    dim3 g1(NG / BN, M_ALL / BM);
    sgemm_x<<<g1, 256>>>(x, Wf, Wi, Wg, Wo, bf, bi, bg, bo);

    long long need = (long long)T_STEPS * BH + 2LL * BH;
    int wf = ((long long)out_size >= need) ? 1 : 0;
    lstm_persist<<<dim3(32, 4), 256, SMEM_PERSIST>>>(out, wf, Wf, Wi, Wg, Wo);
}